// round 9
// baseline (speedup 1.0000x reference)
#include <cuda_runtime.h>
#include <cuda_fp16.h>
#include <cstdint>

#define IMG     224
#define PATCH   16
#define CHN     3
#define GHN     14
#define NPATCH  196
#define M_DIM   12544       // 64*196
#define K_DIM   3840        // 16*16*15
#define N_DIM   768
#define LN_EPS  1e-5f

// fp16 scratch: A (96MB) and converted W (5.9MB)
__device__ __half g_A[(size_t)M_DIM * K_DIM];
__device__ __half g_W[(size_t)N_DIM * K_DIM];

__device__ __forceinline__ uint32_t smem_u32(const void* p) {
    return (uint32_t)__cvta_generic_to_shared(p);
}

// ---------------------------------------------------------------------------
// Kernel 1: gather shifted patches -> fp16 A[M][K], smem-staged.
// CTA = one (b, gi) strip. Stage x rows [gi*16-4, gi*16+20) x 3ch in smem
// (out-of-image rows zeroed -> h-bounds handled for free), then write
// 14 patches x 480 coalesced 16B chunks.
// ---------------------------------------------------------------------------
#define GATHER_SMEM (3 * 24 * 224 * 4)   // 64512 B

__global__ __launch_bounds__(256) void gather_f16(const float* __restrict__ x) {
    extern __shared__ float xs[];              // [3][24][224]
    const int bgi = blockIdx.x;                // 0..895
    const int b  = bgi / GHN;
    const int gi = bgi - b * GHN;
    const int t  = threadIdx.x;

    // stage: 72 rows of 224 floats, coalesced; zero pad out-of-image rows
    for (int row = 0; row < 72; row++) {
        const int c = row / 24, r = row - c * 24;
        const int h = gi * PATCH - 4 + r;
        if (t < IMG) {
            float v = 0.0f;
            if ((unsigned)h < IMG)
                v = x[((size_t)(b * CHN + c) * IMG + h) * IMG + t];
            xs[(c * 24 + r) * IMG + t] = v;
        }
    }
    __syncthreads();

    // emit: 14 patches * 480 chunks = 6720 chunks of 8 halfs
    const size_t outbase = ((size_t)b * NPATCH + gi * GHN) * K_DIM;
    for (int i = 0; i < 27; i++) {
        const int idx = i * 256 + t;
        if (idx >= 6720) break;
        const int gj    = idx / 480;
        const int chunk = idx - gj * 480;
        const int d0    = chunk * 8;
        int pp = d0 / 15;
        int c5 = d0 - pp * 15;
        const int basew = gj * PATCH;

        union { __half h[8]; uint4 v; } out;
#pragma unroll
        for (int j = 0; j < 8; j++) {
            const int s  = c5 / 3;
            const int c  = c5 - 3 * s;
            const int ph = pp >> 4, pw = pp & 15;
            const int dx = (s == 2) ? 4 : ((s == 4) ? -4 : 0);
            const int dy = (s == 1) ? 4 : ((s == 3) ? -4 : 0);
            const int hp = ph - dx + 4;          // 0..23, always in smem
            const int w  = basew + pw - dy;      // needs image bound check
            float v = 0.0f;
            if ((unsigned)w < IMG) v = xs[(c * 24 + hp) * IMG + w];
            out.h[j] = __float2half(v);
            if (++c5 == 15) { c5 = 0; pp++; }
        }
        *(uint4*)(g_A + outbase + (size_t)gj * K_DIM + d0) = out.v;
    }
}

// ---------------------------------------------------------------------------
// Kernel 1b: convert proj_w (f32) -> g_W (f16)
// ---------------------------------------------------------------------------
__global__ __launch_bounds__(256) void wconv_f16(const float* __restrict__ w) {
    unsigned c = blockIdx.x * 256u + threadIdx.x;       // < 368,640 chunks of 8
    const float4 f0 = *(const float4*)(w + (size_t)c * 8);
    const float4 f1 = *(const float4*)(w + (size_t)c * 8 + 4);
    union { __half h[8]; uint4 v; } out;
    out.h[0] = __float2half(f0.x); out.h[1] = __float2half(f0.y);
    out.h[2] = __float2half(f0.z); out.h[3] = __float2half(f0.w);
    out.h[4] = __float2half(f1.x); out.h[5] = __float2half(f1.y);
    out.h[6] = __float2half(f1.z); out.h[7] = __float2half(f1.w);
    *(uint4*)(g_W + (size_t)c * 8) = out.v;
}

// ---------------------------------------------------------------------------
// Kernel 2: mma.sync GEMM  C[M,768] = A[M,K] * W[768,K]^T  (f16 in, f32 acc)
// BM=128, BN=256, BK=32, 512 threads.
// 4-stage cp.async ring, ONE __syncthreads per k-iteration:
//   top barrier certifies (a) stage s data landed (wait_group 2) and
//   (b) stage s-1 consumed by all threads -> buffer (s+3)&3 == (s-1)&3 free.
// ---------------------------------------------------------------------------
#define BM 128
#define BN 256
#define BKG 32
#define NKSTAGE (K_DIM / BKG)    // 120
#define ROWB   80                // bytes per smem row (64 data + 16 pad)
#define A_SZ   (BM * ROWB)       // 10240
#define B_SZ   (BN * ROWB)       // 20480
#define STG_SZ (A_SZ + B_SZ)     // 30720
#define GEMM_SMEM (4 * STG_SZ)   // 122880

__device__ __forceinline__ void ldsm4(uint32_t addr, uint32_t& r0, uint32_t& r1,
                                      uint32_t& r2, uint32_t& r3) {
    asm volatile("ldmatrix.sync.aligned.m8n8.x4.shared.b16 {%0,%1,%2,%3}, [%4];"
                 : "=r"(r0), "=r"(r1), "=r"(r2), "=r"(r3) : "r"(addr));
}

__device__ __forceinline__ void mma16816(float& c0, float& c1, float& c2, float& c3,
                                         uint32_t a0, uint32_t a1, uint32_t a2, uint32_t a3,
                                         uint32_t b0, uint32_t b1) {
    asm volatile(
        "mma.sync.aligned.m16n8k16.row.col.f32.f16.f16.f32 "
        "{%0,%1,%2,%3}, {%4,%5,%6,%7}, {%8,%9}, {%0,%1,%2,%3};"
        : "+f"(c0), "+f"(c1), "+f"(c2), "+f"(c3)
        : "r"(a0), "r"(a1), "r"(a2), "r"(a3), "r"(b0), "r"(b1));
}

__global__ __launch_bounds__(512, 1) void gemm_hmma(float* __restrict__ Cout) {
    extern __shared__ char smem[];
    const uint32_t sb = smem_u32(smem);
    const int tid = threadIdx.x;
    const int bn = blockIdx.x;            // 0..2
    const int bm = blockIdx.y;            // 0..97
    const int wid = tid >> 5, lane = tid & 31;
    const int wm = wid >> 3;              // 0..1  (64 rows each)
    const int wn = wid & 7;               // 0..7  (32 cols each)

    const __half* Ab = g_A + (size_t)bm * BM * K_DIM;
    const __half* Wb = g_W + (size_t)bn * BN * K_DIM;

#define FILL(buf, k0) do {                                                       \
    uint32_t _as = sb + (uint32_t)(buf) * STG_SZ;                                \
    { int _r = tid >> 2, _c = tid & 3;                                           \
      asm volatile("cp.async.cg.shared.global [%0], [%1], 16;"                   \
        :: "r"(_as + _r * ROWB + _c * 16),                                       \
           "l"((const void*)(Ab + (size_t)_r * K_DIM + (k0) + _c * 8))); }       \
    uint32_t _bs = _as + A_SZ;                                                   \
    _Pragma("unroll")                                                            \
    for (int _i = 0; _i < 2; _i++) {                                             \
        int _id = tid + _i * 512; int _r = _id >> 2, _c = _id & 3;               \
        asm volatile("cp.async.cg.shared.global [%0], [%1], 16;"                 \
          :: "r"(_bs + _r * ROWB + _c * 16),                                     \
             "l"((const void*)(Wb + (size_t)_r * K_DIM + (k0) + _c * 8)));       \
    }                                                                            \
    asm volatile("cp.async.commit_group;");                                      \
} while (0)

    FILL(0, 0); FILL(1, BKG); FILL(2, 2 * BKG);

    float acc[4][4][4];
#pragma unroll
    for (int i = 0; i < 4; i++)
#pragma unroll
        for (int j = 0; j < 4; j++)
#pragma unroll
            for (int q = 0; q < 4; q++) acc[i][j][q] = 0.0f;

    const int lrow = lane & 15;           // ldmatrix row select
    const int lhalf = lane >> 4;          // k-half select (0/1) -> +16B

    for (int s = 0; s < NKSTAGE; s++) {
        asm volatile("cp.async.wait_group 2;");
        __syncthreads();
        if (s + 3 < NKSTAGE) {
            FILL((s + 3) & 3, (s + 3) * BKG);
        } else {
            asm volatile("cp.async.commit_group;");
        }
        const int buf = s & 3;
        const uint32_t as = sb + buf * STG_SZ;
        const uint32_t bs = as + A_SZ;

#pragma unroll
        for (int ks = 0; ks < 2; ks++) {
            uint32_t a[4][4];
#pragma unroll
            for (int mt = 0; mt < 4; mt++) {
                uint32_t ad = as + (uint32_t)(wm * 64 + mt * 16 + lrow) * ROWB
                              + ks * 32 + lhalf * 16;
                ldsm4(ad, a[mt][0], a[mt][1], a[mt][2], a[mt][3]);
            }
            uint32_t bg[2][4];
#pragma unroll
            for (int g = 0; g < 2; g++) {
                uint32_t bd = bs + (uint32_t)(wn * 32 + g * 16 + lrow) * ROWB
                              + ks * 32 + lhalf * 16;
                ldsm4(bd, bg[g][0], bg[g][1], bg[g][2], bg[g][3]);
            }
#pragma unroll
            for (int mt = 0; mt < 4; mt++)
#pragma unroll
                for (int nt = 0; nt < 4; nt++) {
                    const int g = nt >> 1, pr = nt & 1;
                    mma16816(acc[mt][nt][0], acc[mt][nt][1], acc[mt][nt][2], acc[mt][nt][3],
                             a[mt][0], a[mt][1], a[mt][2], a[mt][3],
                             bg[g][pr], bg[g][pr + 2]);
                }
        }
    }

    // epilogue: direct register -> gmem stores
    const int mbase = bm * BM + wm * 64 + (lane >> 2);
    const int nbase = bn * BN + wn * 32 + 2 * (lane & 3);
#pragma unroll
    for (int mt = 0; mt < 4; mt++) {
#pragma unroll
        for (int nt = 0; nt < 4; nt++) {
            float2 v0 = make_float2(acc[mt][nt][0], acc[mt][nt][1]);
            float2 v1 = make_float2(acc[mt][nt][2], acc[mt][nt][3]);
            *(float2*)(Cout + (size_t)(mbase + mt * 16) * N_DIM + nbase + nt * 8) = v0;
            *(float2*)(Cout + (size_t)(mbase + mt * 16 + 8) * N_DIM + nbase + nt * 8) = v1;
        }
    }
}

// ---------------------------------------------------------------------------
// Kernel 3: LayerNorm, warp-per-row (no block barrier), +bias, in-place
// ---------------------------------------------------------------------------
__global__ __launch_bounds__(256) void ln_kernel(float* __restrict__ hbuf,
                                                 const float* __restrict__ pbias,
                                                 const float* __restrict__ gamma,
                                                 const float* __restrict__ beta) {
    const int warp = threadIdx.x >> 5, lane = threadIdx.x & 31;
    const size_t row = (size_t)blockIdx.x * 8 + warp;
    float* p = hbuf + row * N_DIM;

    float v[24];
    float s = 0.0f, q = 0.0f;
#pragma unroll
    for (int i = 0; i < 6; i++) {
        const int off = i * 128 + lane * 4;
        float4 a  = *(const float4*)(p + off);
        float4 bb = *(const float4*)(pbias + off);
        a.x += bb.x; a.y += bb.y; a.z += bb.z; a.w += bb.w;
        v[i * 4 + 0] = a.x; v[i * 4 + 1] = a.y;
        v[i * 4 + 2] = a.z; v[i * 4 + 3] = a.w;
        s += a.x + a.y + a.z + a.w;
        q += a.x * a.x + a.y * a.y + a.z * a.z + a.w * a.w;
    }
#pragma unroll
    for (int o = 16; o > 0; o >>= 1) {
        s += __shfl_xor_sync(0xffffffffu, s, o);
        q += __shfl_xor_sync(0xffffffffu, q, o);
    }
    const float mean = s * (1.0f / (float)N_DIM);
    const float var  = q * (1.0f / (float)N_DIM) - mean * mean;
    const float rstd = rsqrtf(var + LN_EPS);

#pragma unroll
    for (int i = 0; i < 6; i++) {
        const int off = i * 128 + lane * 4;
        float4 gg = *(const float4*)(gamma + off);
        float4 be = *(const float4*)(beta + off);
        float4 o;
        o.x = (v[i * 4 + 0] - mean) * rstd * gg.x + be.x;
        o.y = (v[i * 4 + 1] - mean) * rstd * gg.y + be.y;
        o.z = (v[i * 4 + 2] - mean) * rstd * gg.z + be.z;
        o.w = (v[i * 4 + 3] - mean) * rstd * gg.w + be.w;
        *(float4*)(p + off) = o;
    }
}

// ---------------------------------------------------------------------------
extern "C" void kernel_launch(void* const* d_in, const int* in_sizes, int n_in,
                              void* d_out, int out_size) {
    const float* x     = (const float*)d_in[0];
    const float* pw    = (const float*)d_in[1];
    const float* pb    = (const float*)d_in[2];
    const float* gamma = (const float*)d_in[3];
    const float* beta  = (const float*)d_in[4];
    float* out = (float*)d_out;

    cudaFuncSetAttribute(gather_f16,
                         cudaFuncAttributeMaxDynamicSharedMemorySize, GATHER_SMEM);
    cudaFuncSetAttribute(gemm_hmma,
                         cudaFuncAttributeMaxDynamicSharedMemorySize, GEMM_SMEM);

    gather_f16<<<64 * GHN, 256, GATHER_SMEM>>>(x);     // 896 CTAs
    wconv_f16<<<1440, 256>>>(pw);                      // 368,640 chunks

    dim3 grid(N_DIM / BN, M_DIM / BM);                 // (3, 98)
    gemm_hmma<<<grid, 512, GEMM_SMEM>>>(out);

    ln_kernel<<<M_DIM / 8, 256>>>(out, pb, gamma, beta);
}

// round 10
// speedup vs baseline: 1.2301x; 1.2301x over previous
#include <cuda_runtime.h>
#include <cuda_fp16.h>
#include <cstdint>

#define IMG     224
#define PATCH   16
#define CHN     3
#define GHN     14
#define NPATCH  196
#define M_DIM   12544       // 64*196
#define K_DIM   3840        // 16*16*15
#define N_DIM   768
#define LN_EPS  1e-5f

// fp16 scratch: A (96MB) and converted W (5.9MB)
__device__ __half g_A[(size_t)M_DIM * K_DIM];
__device__ __half g_W[(size_t)N_DIM * K_DIM];

__device__ __forceinline__ uint32_t smem_u32(const void* p) {
    return (uint32_t)__cvta_generic_to_shared(p);
}

// ---------------------------------------------------------------------------
// Kernel 1: gather shifted patches -> fp16 A[M][K].  One thread per 16B chunk.
// (round-8 version: measured as part of the 385us config)
// ---------------------------------------------------------------------------
__global__ __launch_bounds__(256) void gather_f16(const float* __restrict__ x) {
    unsigned chunk = blockIdx.x * 256u + threadIdx.x;   // < 6,021,120
    unsigned row = chunk / 480u;
    unsigned d0  = (chunk - row * 480u) * 8u;
    unsigned b = row / (unsigned)NPATCH;
    unsigned n = row - b * NPATCH;
    int gi = (int)(n / GHN), gj = (int)(n - (n / GHN) * GHN);
    unsigned pp = d0 / 15u;
    int c5 = (int)(d0 - pp * 15u);
    const int baseh = gi * PATCH, basew = gj * PATCH;
    const float* xb = x + (size_t)b * CHN * IMG * IMG;

    union { __half h[8]; uint4 v; } out;
#pragma unroll
    for (int j = 0; j < 8; j++) {
        int s = c5 / 3;
        int c = c5 - 3 * s;
        int ph = (int)(pp >> 4), pw = (int)(pp & 15u);
        int dx = (s == 2) ? 4 : ((s == 4) ? -4 : 0);
        int dy = (s == 1) ? 4 : ((s == 3) ? -4 : 0);
        int h = baseh + ph - dx;
        int w = basew + pw - dy;
        float v = 0.0f;
        if ((unsigned)h < IMG && (unsigned)w < IMG)
            v = xb[c * (IMG * IMG) + h * IMG + w];
        out.h[j] = __float2half(v);
        if (++c5 == 15) { c5 = 0; pp++; }
    }
    *(uint4*)(g_A + (size_t)chunk * 8) = out.v;
}

// ---------------------------------------------------------------------------
// Kernel 1b: convert proj_w (f32) -> g_W (f16)
// ---------------------------------------------------------------------------
__global__ __launch_bounds__(256) void wconv_f16(const float* __restrict__ w) {
    unsigned c = blockIdx.x * 256u + threadIdx.x;       // < 368,640 chunks of 8
    const float4 f0 = *(const float4*)(w + (size_t)c * 8);
    const float4 f1 = *(const float4*)(w + (size_t)c * 8 + 4);
    union { __half h[8]; uint4 v; } out;
    out.h[0] = __float2half(f0.x); out.h[1] = __float2half(f0.y);
    out.h[2] = __float2half(f0.z); out.h[3] = __float2half(f0.w);
    out.h[4] = __float2half(f1.x); out.h[5] = __float2half(f1.y);
    out.h[6] = __float2half(f1.z); out.h[7] = __float2half(f1.w);
    *(uint4*)(g_W + (size_t)c * 8) = out.v;
}

// ---------------------------------------------------------------------------
// Kernel 2: mma.sync GEMM  C[M,768] = A[M,K] * W[768,K]^T  (f16 in, f32 acc)
// BM=128, BN=256, BK=32, 512 threads.
// 4-stage cp.async ring, ONE __syncthreads per k-iteration.
// ---------------------------------------------------------------------------
#define BM 128
#define BN 256
#define BKG 32
#define NKSTAGE (K_DIM / BKG)    // 120
#define ROWB   80                // bytes per smem row (64 data + 16 pad)
#define A_SZ   (BM * ROWB)       // 10240
#define B_SZ   (BN * ROWB)       // 20480
#define STG_SZ (A_SZ + B_SZ)     // 30720
#define GEMM_SMEM (4 * STG_SZ)   // 122880

__device__ __forceinline__ void ldsm4(uint32_t addr, uint32_t& r0, uint32_t& r1,
                                      uint32_t& r2, uint32_t& r3) {
    asm volatile("ldmatrix.sync.aligned.m8n8.x4.shared.b16 {%0,%1,%2,%3}, [%4];"
                 : "=r"(r0), "=r"(r1), "=r"(r2), "=r"(r3) : "r"(addr));
}

__device__ __forceinline__ void mma16816(float& c0, float& c1, float& c2, float& c3,
                                         uint32_t a0, uint32_t a1, uint32_t a2, uint32_t a3,
                                         uint32_t b0, uint32_t b1) {
    asm volatile(
        "mma.sync.aligned.m16n8k16.row.col.f32.f16.f16.f32 "
        "{%0,%1,%2,%3}, {%4,%5,%6,%7}, {%8,%9}, {%0,%1,%2,%3};"
        : "+f"(c0), "+f"(c1), "+f"(c2), "+f"(c3)
        : "r"(a0), "r"(a1), "r"(a2), "r"(a3), "r"(b0), "r"(b1));
}

__global__ __launch_bounds__(512, 1) void gemm_hmma(float* __restrict__ Cout) {
    extern __shared__ char smem[];
    const uint32_t sb = smem_u32(smem);
    const int tid = threadIdx.x;
    const int bn = blockIdx.x;            // 0..2
    const int bm = blockIdx.y;            // 0..97
    const int wid = tid >> 5, lane = tid & 31;
    const int wm = wid >> 3;              // 0..1  (64 rows each)
    const int wn = wid & 7;               // 0..7  (32 cols each)

    const __half* Ab = g_A + (size_t)bm * BM * K_DIM;
    const __half* Wb = g_W + (size_t)bn * BN * K_DIM;

#define FILL(buf, k0) do {                                                       \
    uint32_t _as = sb + (uint32_t)(buf) * STG_SZ;                                \
    { int _r = tid >> 2, _c = tid & 3;                                           \
      asm volatile("cp.async.cg.shared.global [%0], [%1], 16;"                   \
        :: "r"(_as + _r * ROWB + _c * 16),                                       \
           "l"((const void*)(Ab + (size_t)_r * K_DIM + (k0) + _c * 8))); }       \
    uint32_t _bs = _as + A_SZ;                                                   \
    _Pragma("unroll")                                                            \
    for (int _i = 0; _i < 2; _i++) {                                             \
        int _id = tid + _i * 512; int _r = _id >> 2, _c = _id & 3;               \
        asm volatile("cp.async.cg.shared.global [%0], [%1], 16;"                 \
          :: "r"(_bs + _r * ROWB + _c * 16),                                     \
             "l"((const void*)(Wb + (size_t)_r * K_DIM + (k0) + _c * 8)));       \
    }                                                                            \
    asm volatile("cp.async.commit_group;");                                      \
} while (0)

    FILL(0, 0); FILL(1, BKG); FILL(2, 2 * BKG);

    float acc[4][4][4];
#pragma unroll
    for (int i = 0; i < 4; i++)
#pragma unroll
        for (int j = 0; j < 4; j++)
#pragma unroll
            for (int q = 0; q < 4; q++) acc[i][j][q] = 0.0f;

    const int lrow = lane & 15;           // ldmatrix row select
    const int lhalf = lane >> 4;          // k-half select (0/1) -> +16B

    for (int s = 0; s < NKSTAGE; s++) {
        asm volatile("cp.async.wait_group 2;");
        __syncthreads();
        if (s + 3 < NKSTAGE) {
            FILL((s + 3) & 3, (s + 3) * BKG);
        } else {
            asm volatile("cp.async.commit_group;");
        }
        const int buf = s & 3;
        const uint32_t as = sb + buf * STG_SZ;
        const uint32_t bs = as + A_SZ;

#pragma unroll
        for (int ks = 0; ks < 2; ks++) {
            uint32_t a[4][4];
#pragma unroll
            for (int mt = 0; mt < 4; mt++) {
                uint32_t ad = as + (uint32_t)(wm * 64 + mt * 16 + lrow) * ROWB
                              + ks * 32 + lhalf * 16;
                ldsm4(ad, a[mt][0], a[mt][1], a[mt][2], a[mt][3]);
            }
            uint32_t bg[2][4];
#pragma unroll
            for (int g = 0; g < 2; g++) {
                uint32_t bd = bs + (uint32_t)(wn * 32 + g * 16 + lrow) * ROWB
                              + ks * 32 + lhalf * 16;
                ldsm4(bd, bg[g][0], bg[g][1], bg[g][2], bg[g][3]);
            }
#pragma unroll
            for (int mt = 0; mt < 4; mt++)
#pragma unroll
                for (int nt = 0; nt < 4; nt++) {
                    const int g = nt >> 1, pr = nt & 1;
                    mma16816(acc[mt][nt][0], acc[mt][nt][1], acc[mt][nt][2], acc[mt][nt][3],
                             a[mt][0], a[mt][1], a[mt][2], a[mt][3],
                             bg[g][pr], bg[g][pr + 2]);
                }
        }
    }

    // epilogue: direct register -> gmem stores
    const int mbase = bm * BM + wm * 64 + (lane >> 2);
    const int nbase = bn * BN + wn * 32 + 2 * (lane & 3);
#pragma unroll
    for (int mt = 0; mt < 4; mt++) {
#pragma unroll
        for (int nt = 0; nt < 4; nt++) {
            float2 v0 = make_float2(acc[mt][nt][0], acc[mt][nt][1]);
            float2 v1 = make_float2(acc[mt][nt][2], acc[mt][nt][3]);
            *(float2*)(Cout + (size_t)(mbase + mt * 16) * N_DIM + nbase + nt * 8) = v0;
            *(float2*)(Cout + (size_t)(mbase + mt * 16 + 8) * N_DIM + nbase + nt * 8) = v1;
        }
    }
}

// ---------------------------------------------------------------------------
// Kernel 3: LayerNorm, warp-per-row (no block barrier), +bias, in-place
// (round-9 version: measured 15.4us, keep)
// ---------------------------------------------------------------------------
__global__ __launch_bounds__(256) void ln_kernel(float* __restrict__ hbuf,
                                                 const float* __restrict__ pbias,
                                                 const float* __restrict__ gamma,
                                                 const float* __restrict__ beta) {
    const int warp = threadIdx.x >> 5, lane = threadIdx.x & 31;
    const size_t row = (size_t)blockIdx.x * 8 + warp;
    float* p = hbuf + row * N_DIM;

    float v[24];
    float s = 0.0f, q = 0.0f;
#pragma unroll
    for (int i = 0; i < 6; i++) {
        const int off = i * 128 + lane * 4;
        float4 a  = *(const float4*)(p + off);
        float4 bb = *(const float4*)(pbias + off);
        a.x += bb.x; a.y += bb.y; a.z += bb.z; a.w += bb.w;
        v[i * 4 + 0] = a.x; v[i * 4 + 1] = a.y;
        v[i * 4 + 2] = a.z; v[i * 4 + 3] = a.w;
        s += a.x + a.y + a.z + a.w;
        q += a.x * a.x + a.y * a.y + a.z * a.z + a.w * a.w;
    }
#pragma unroll
    for (int o = 16; o > 0; o >>= 1) {
        s += __shfl_xor_sync(0xffffffffu, s, o);
        q += __shfl_xor_sync(0xffffffffu, q, o);
    }
    const float mean = s * (1.0f / (float)N_DIM);
    const float var  = q * (1.0f / (float)N_DIM) - mean * mean;
    const float rstd = rsqrtf(var + LN_EPS);

#pragma unroll
    for (int i = 0; i < 6; i++) {
        const int off = i * 128 + lane * 4;
        float4 gg = *(const float4*)(gamma + off);
        float4 be = *(const float4*)(beta + off);
        float4 o;
        o.x = (v[i * 4 + 0] - mean) * rstd * gg.x + be.x;
        o.y = (v[i * 4 + 1] - mean) * rstd * gg.y + be.y;
        o.z = (v[i * 4 + 2] - mean) * rstd * gg.z + be.z;
        o.w = (v[i * 4 + 3] - mean) * rstd * gg.w + be.w;
        *(float4*)(p + off) = o;
    }
}

// ---------------------------------------------------------------------------
extern "C" void kernel_launch(void* const* d_in, const int* in_sizes, int n_in,
                              void* d_out, int out_size) {
    const float* x     = (const float*)d_in[0];
    const float* pw    = (const float*)d_in[1];
    const float* pb    = (const float*)d_in[2];
    const float* gamma = (const float*)d_in[3];
    const float* beta  = (const float*)d_in[4];
    float* out = (float*)d_out;

    cudaFuncSetAttribute(gemm_hmma,
                         cudaFuncAttributeMaxDynamicSharedMemorySize, GEMM_SMEM);

    gather_f16<<<23520, 256>>>(x);                     // 6,021,120 chunks
    wconv_f16<<<1440, 256>>>(pw);                      // 368,640 chunks

    dim3 grid(N_DIM / BN, M_DIM / BM);                 // (3, 98)
    gemm_hmma<<<grid, 512, GEMM_SMEM>>>(out);

    ln_kernel<<<M_DIM / 8, 256>>>(out, pb, gamma, beta);
}

// round 11
// speedup vs baseline: 1.2349x; 1.0039x over previous
#include <cuda_runtime.h>
#include <cuda_fp16.h>
#include <cstdint>

#define IMG     224
#define PATCH   16
#define CHN     3
#define GHN     14
#define NPATCH  196
#define M_DIM   12544       // 64*196
#define K_DIM   3840        // 16*16*15
#define N_DIM   768
#define LN_EPS  1e-5f

// fp16 scratch: A (96MB) and converted W (5.9MB)
__device__ __half g_A[(size_t)M_DIM * K_DIM];
__device__ __half g_W[(size_t)N_DIM * K_DIM];

__device__ __forceinline__ uint32_t smem_u32(const void* p) {
    return (uint32_t)__cvta_generic_to_shared(p);
}

// ---------------------------------------------------------------------------
// Kernel 1: gather shifted patches -> fp16 A[M][K].  One thread per 16B chunk.
// (round-8 version: measured as part of the 385us config)
// ---------------------------------------------------------------------------
__global__ __launch_bounds__(256) void gather_f16(const float* __restrict__ x) {
    unsigned chunk = blockIdx.x * 256u + threadIdx.x;   // < 6,021,120
    unsigned row = chunk / 480u;
    unsigned d0  = (chunk - row * 480u) * 8u;
    unsigned b = row / (unsigned)NPATCH;
    unsigned n = row - b * NPATCH;
    int gi = (int)(n / GHN), gj = (int)(n - (n / GHN) * GHN);
    unsigned pp = d0 / 15u;
    int c5 = (int)(d0 - pp * 15u);
    const int baseh = gi * PATCH, basew = gj * PATCH;
    const float* xb = x + (size_t)b * CHN * IMG * IMG;

    union { __half h[8]; uint4 v; } out;
#pragma unroll
    for (int j = 0; j < 8; j++) {
        int s = c5 / 3;
        int c = c5 - 3 * s;
        int ph = (int)(pp >> 4), pw = (int)(pp & 15u);
        int dx = (s == 2) ? 4 : ((s == 4) ? -4 : 0);
        int dy = (s == 1) ? 4 : ((s == 3) ? -4 : 0);
        int h = baseh + ph - dx;
        int w = basew + pw - dy;
        float v = 0.0f;
        if ((unsigned)h < IMG && (unsigned)w < IMG)
            v = xb[c * (IMG * IMG) + h * IMG + w];
        out.h[j] = __float2half(v);
        if (++c5 == 15) { c5 = 0; pp++; }
    }
    *(uint4*)(g_A + (size_t)chunk * 8) = out.v;
}

// ---------------------------------------------------------------------------
// Kernel 1b: convert proj_w (f32) -> g_W (f16)
// ---------------------------------------------------------------------------
__global__ __launch_bounds__(256) void wconv_f16(const float* __restrict__ w) {
    unsigned c = blockIdx.x * 256u + threadIdx.x;       // < 368,640 chunks of 8
    const float4 f0 = *(const float4*)(w + (size_t)c * 8);
    const float4 f1 = *(const float4*)(w + (size_t)c * 8 + 4);
    union { __half h[8]; uint4 v; } out;
    out.h[0] = __float2half(f0.x); out.h[1] = __float2half(f0.y);
    out.h[2] = __float2half(f0.z); out.h[3] = __float2half(f0.w);
    out.h[4] = __float2half(f1.x); out.h[5] = __float2half(f1.y);
    out.h[6] = __float2half(f1.z); out.h[7] = __float2half(f1.w);
    *(uint4*)(g_W + (size_t)c * 8) = out.v;
}

// ---------------------------------------------------------------------------
// Kernel 2: mma.sync GEMM  C[M,768] = A[M,K] * W[768,K]^T  (f16 in, f32 acc)
// BM=128, BN=256, BK=32, 512 threads.
// 4-stage cp.async ring, ONE __syncthreads per k-iteration.
// ---------------------------------------------------------------------------
#define BM 128
#define BN 256
#define BKG 32
#define NKSTAGE (K_DIM / BKG)    // 120
#define ROWB   80                // bytes per smem row (64 data + 16 pad)
#define A_SZ   (BM * ROWB)       // 10240
#define B_SZ   (BN * ROWB)       // 20480
#define STG_SZ (A_SZ + B_SZ)     // 30720
#define GEMM_SMEM (4 * STG_SZ)   // 122880

__device__ __forceinline__ void ldsm4(uint32_t addr, uint32_t& r0, uint32_t& r1,
                                      uint32_t& r2, uint32_t& r3) {
    asm volatile("ldmatrix.sync.aligned.m8n8.x4.shared.b16 {%0,%1,%2,%3}, [%4];"
                 : "=r"(r0), "=r"(r1), "=r"(r2), "=r"(r3) : "r"(addr));
}

__device__ __forceinline__ void mma16816(float& c0, float& c1, float& c2, float& c3,
                                         uint32_t a0, uint32_t a1, uint32_t a2, uint32_t a3,
                                         uint32_t b0, uint32_t b1) {
    asm volatile(
        "mma.sync.aligned.m16n8k16.row.col.f32.f16.f16.f32 "
        "{%0,%1,%2,%3}, {%4,%5,%6,%7}, {%8,%9}, {%0,%1,%2,%3};"
        : "+f"(c0), "+f"(c1), "+f"(c2), "+f"(c3)
        : "r"(a0), "r"(a1), "r"(a2), "r"(a3), "r"(b0), "r"(b1));
}

__global__ __launch_bounds__(512, 1) void gemm_hmma(float* __restrict__ Cout) {
    extern __shared__ char smem[];
    const uint32_t sb = smem_u32(smem);
    const int tid = threadIdx.x;
    const int bn = blockIdx.x;            // 0..2
    const int bm = blockIdx.y;            // 0..97
    const int wid = tid >> 5, lane = tid & 31;
    const int wm = wid >> 3;              // 0..1  (64 rows each)
    const int wn = wid & 7;               // 0..7  (32 cols each)

    const __half* Ab = g_A + (size_t)bm * BM * K_DIM;
    const __half* Wb = g_W + (size_t)bn * BN * K_DIM;

#define FILL(buf, k0) do {                                                       \
    uint32_t _as = sb + (uint32_t)(buf) * STG_SZ;                                \
    { int _r = tid >> 2, _c = tid & 3;                                           \
      asm volatile("cp.async.cg.shared.global [%0], [%1], 16;"                   \
        :: "r"(_as + _r * ROWB + _c * 16),                                       \
           "l"((const void*)(Ab + (size_t)_r * K_DIM + (k0) + _c * 8))); }       \
    uint32_t _bs = _as + A_SZ;                                                   \
    _Pragma("unroll")                                                            \
    for (int _i = 0; _i < 2; _i++) {                                             \
        int _id = tid + _i * 512; int _r = _id >> 2, _c = _id & 3;               \
        asm volatile("cp.async.cg.shared.global [%0], [%1], 16;"                 \
          :: "r"(_bs + _r * ROWB + _c * 16),                                     \
             "l"((const void*)(Wb + (size_t)_r * K_DIM + (k0) + _c * 8)));       \
    }                                                                            \
    asm volatile("cp.async.commit_group;");                                      \
} while (0)

    FILL(0, 0); FILL(1, BKG); FILL(2, 2 * BKG);

    float acc[4][4][4];
#pragma unroll
    for (int i = 0; i < 4; i++)
#pragma unroll
        for (int j = 0; j < 4; j++)
#pragma unroll
            for (int q = 0; q < 4; q++) acc[i][j][q] = 0.0f;

    const int lrow = lane & 15;           // ldmatrix row select
    const int lhalf = lane >> 4;          // k-half select (0/1) -> +16B

    for (int s = 0; s < NKSTAGE; s++) {
        asm volatile("cp.async.wait_group 2;");
        __syncthreads();
        if (s + 3 < NKSTAGE) {
            FILL((s + 3) & 3, (s + 3) * BKG);
        } else {
            asm volatile("cp.async.commit_group;");
        }
        const int buf = s & 3;
        const uint32_t as = sb + buf * STG_SZ;
        const uint32_t bs = as + A_SZ;

#pragma unroll
        for (int ks = 0; ks < 2; ks++) {
            uint32_t a[4][4];
#pragma unroll
            for (int mt = 0; mt < 4; mt++) {
                uint32_t ad = as + (uint32_t)(wm * 64 + mt * 16 + lrow) * ROWB
                              + ks * 32 + lhalf * 16;
                ldsm4(ad, a[mt][0], a[mt][1], a[mt][2], a[mt][3]);
            }
            uint32_t bg[2][4];
#pragma unroll
            for (int g = 0; g < 2; g++) {
                uint32_t bd = bs + (uint32_t)(wn * 32 + g * 16 + lrow) * ROWB
                              + ks * 32 + lhalf * 16;
                ldsm4(bd, bg[g][0], bg[g][1], bg[g][2], bg[g][3]);
            }
#pragma unroll
            for (int mt = 0; mt < 4; mt++)
#pragma unroll
                for (int nt = 0; nt < 4; nt++) {
                    const int g = nt >> 1, pr = nt & 1;
                    mma16816(acc[mt][nt][0], acc[mt][nt][1], acc[mt][nt][2], acc[mt][nt][3],
                             a[mt][0], a[mt][1], a[mt][2], a[mt][3],
                             bg[g][pr], bg[g][pr + 2]);
                }
        }
    }

    // epilogue: direct register -> gmem stores
    const int mbase = bm * BM + wm * 64 + (lane >> 2);
    const int nbase = bn * BN + wn * 32 + 2 * (lane & 3);
#pragma unroll
    for (int mt = 0; mt < 4; mt++) {
#pragma unroll
        for (int nt = 0; nt < 4; nt++) {
            float2 v0 = make_float2(acc[mt][nt][0], acc[mt][nt][1]);
            float2 v1 = make_float2(acc[mt][nt][2], acc[mt][nt][3]);
            *(float2*)(Cout + (size_t)(mbase + mt * 16) * N_DIM + nbase + nt * 8) = v0;
            *(float2*)(Cout + (size_t)(mbase + mt * 16 + 8) * N_DIM + nbase + nt * 8) = v1;
        }
    }
}

// ---------------------------------------------------------------------------
// Kernel 3: LayerNorm, warp-per-row (no block barrier), +bias, in-place
// (round-9 version: measured 15.4us, keep)
// ---------------------------------------------------------------------------
__global__ __launch_bounds__(256) void ln_kernel(float* __restrict__ hbuf,
                                                 const float* __restrict__ pbias,
                                                 const float* __restrict__ gamma,
                                                 const float* __restrict__ beta) {
    const int warp = threadIdx.x >> 5, lane = threadIdx.x & 31;
    const size_t row = (size_t)blockIdx.x * 8 + warp;
    float* p = hbuf + row * N_DIM;

    float v[24];
    float s = 0.0f, q = 0.0f;
#pragma unroll
    for (int i = 0; i < 6; i++) {
        const int off = i * 128 + lane * 4;
        float4 a  = *(const float4*)(p + off);
        float4 bb = *(const float4*)(pbias + off);
        a.x += bb.x; a.y += bb.y; a.z += bb.z; a.w += bb.w;
        v[i * 4 + 0] = a.x; v[i * 4 + 1] = a.y;
        v[i * 4 + 2] = a.z; v[i * 4 + 3] = a.w;
        s += a.x + a.y + a.z + a.w;
        q += a.x * a.x + a.y * a.y + a.z * a.z + a.w * a.w;
    }
#pragma unroll
    for (int o = 16; o > 0; o >>= 1) {
        s += __shfl_xor_sync(0xffffffffu, s, o);
        q += __shfl_xor_sync(0xffffffffu, q, o);
    }
    const float mean = s * (1.0f / (float)N_DIM);
    const float var  = q * (1.0f / (float)N_DIM) - mean * mean;
    const float rstd = rsqrtf(var + LN_EPS);

#pragma unroll
    for (int i = 0; i < 6; i++) {
        const int off = i * 128 + lane * 4;
        float4 gg = *(const float4*)(gamma + off);
        float4 be = *(const float4*)(beta + off);
        float4 o;
        o.x = (v[i * 4 + 0] - mean) * rstd * gg.x + be.x;
        o.y = (v[i * 4 + 1] - mean) * rstd * gg.y + be.y;
        o.z = (v[i * 4 + 2] - mean) * rstd * gg.z + be.z;
        o.w = (v[i * 4 + 3] - mean) * rstd * gg.w + be.w;
        *(float4*)(p + off) = o;
    }
}

// ---------------------------------------------------------------------------
extern "C" void kernel_launch(void* const* d_in, const int* in_sizes, int n_in,
                              void* d_out, int out_size) {
    const float* x     = (const float*)d_in[0];
    const float* pw    = (const float*)d_in[1];
    const float* pb    = (const float*)d_in[2];
    const float* gamma = (const float*)d_in[3];
    const float* beta  = (const float*)d_in[4];
    float* out = (float*)d_out;

    cudaFuncSetAttribute(gemm_hmma,
                         cudaFuncAttributeMaxDynamicSharedMemorySize, GEMM_SMEM);

    gather_f16<<<23520, 256>>>(x);                     // 6,021,120 chunks
    wconv_f16<<<1440, 256>>>(pw);                      // 368,640 chunks

    dim3 grid(N_DIM / BN, M_DIM / BM);                 // (3, 98)
    gemm_hmma<<<grid, 512, GEMM_SMEM>>>(out);

    ln_kernel<<<M_DIM / 8, 256>>>(out, pb, gamma, beta);
}